// round 13
// baseline (speedup 1.0000x reference)
#include <cuda_runtime.h>
#include <cuda_fp16.h>
#include <math.h>
#include <stdint.h>

#define SQ 64
#define NB 64
#define NV 10000
#define NVP 10112            // padded to 79*128
#define NE 1024
#define NH 1024
#define MROWS (SQ*NB)        // 4096
#define KDIM 1024
#define NCH 32               // 1024/32 k-chunks
#define NSTAGE 4
#define NT_M 32
#define NT_N 79
#define NTILES (NT_M * NT_N)

// ---------------------------------------------------------------------------
// Device scratch
// ---------------------------------------------------------------------------
__device__ float  g_Xp[MROWS * NH];          // x@W0^T + b0
__device__ __half g_X[MROWS * KDIM];         // gathered emb
__device__ __half g_W0h[NH * KDIM];
__device__ __half g_W1h[NH * KDIM];
__device__ __half g_Wh0h[NH * KDIM];
__device__ __half g_Wh1h[NH * KDIM];
__device__ __half g_Wdh[NVP * KDIM];
__device__ __half g_H0[MROWS * KDIM];        // h0 history
__device__ __half g_H1[MROWS * KDIM];        // h1 history
__device__ __half g_h0i[NB * KDIM];
__device__ __half g_h1i[NB * KDIM];
__device__ unsigned int g_bar0 = 0;
__device__ unsigned int g_bar1 = 0;
__device__ unsigned int g_tile = 0;
__device__ unsigned int g_done = 0;

// ---------------------------------------------------------------------------
// helpers
// ---------------------------------------------------------------------------
__device__ __forceinline__ uint32_t smem_u32(const void* p) {
    uint32_t a;
    asm("{ .reg .u64 t; cvta.to.shared.u64 t, %1; cvt.u32.u64 %0, t; }" : "=r"(a) : "l"(p));
    return a;
}
__device__ __forceinline__ void cpasync16(uint32_t dst, const void* src) {
    asm volatile("cp.async.cg.shared.global [%0], [%1], 16;" :: "r"(dst), "l"(src) : "memory");
}
__device__ __forceinline__ void ldmat4(uint32_t* r, uint32_t addr) {
    asm volatile("ldmatrix.sync.aligned.m8n8.x4.shared.b16 {%0,%1,%2,%3}, [%4];"
                 : "=r"(r[0]), "=r"(r[1]), "=r"(r[2]), "=r"(r[3]) : "r"(addr));
}
__device__ __forceinline__ void ldmat2(uint32_t* r, uint32_t addr) {
    asm volatile("ldmatrix.sync.aligned.m8n8.x2.shared.b16 {%0,%1}, [%2];"
                 : "=r"(r[0]), "=r"(r[1]) : "r"(addr));
}
__device__ __forceinline__ void mma16816(float* c, const uint32_t* a, const uint32_t* b) {
    asm volatile("mma.sync.aligned.m16n8k16.row.col.f32.f16.f16.f32 "
                 "{%0,%1,%2,%3}, {%4,%5,%6,%7}, {%8,%9}, {%0,%1,%2,%3};"
                 : "+f"(c[0]), "+f"(c[1]), "+f"(c[2]), "+f"(c[3])
                 : "r"(a[0]), "r"(a[1]), "r"(a[2]), "r"(a[3]), "r"(b[0]), "r"(b[1]));
}
// tight spin (chain critical path)
__device__ __forceinline__ void spin_ge(const unsigned int* bar, unsigned int target) {
    unsigned int v;
    do {
        asm volatile("ld.global.acquire.gpu.u32 %0, [%1];" : "=r"(v) : "l"(bar) : "memory");
    } while (v < target);
}
// sleepy spin (long waits in the gemm gate)
__device__ __forceinline__ void spin_ge_sleep(const unsigned int* bar, unsigned int target) {
    unsigned int v;
    do {
        asm volatile("ld.global.acquire.gpu.u32 %0, [%1];" : "=r"(v) : "l"(bar) : "memory");
        if (v >= target) break;
        __nanosleep(128);
    } while (true);
}
__device__ __forceinline__ void red_release_add1(unsigned int* bar) {
    asm volatile("red.release.gpu.global.add.u32 [%0], %1;" :: "l"(bar), "r"(1u) : "memory");
}

// ---------------------------------------------------------------------------
// conversion / init kernels (vectorized)
// ---------------------------------------------------------------------------
__global__ void cvtW4_k(const float* __restrict__ W0, const float* __restrict__ Wh0,
                        const float* __restrict__ W1, const float* __restrict__ Wh1,
                        __half* __restrict__ d0, __half* __restrict__ dh0,
                        __half* __restrict__ d1, __half* __restrict__ dh1) {
    int i = blockIdx.x * blockDim.x + threadIdx.x;
    const float* s; __half* d;
    switch (blockIdx.y) {
        case 0:  s = W0;  d = d0;  break;
        case 1:  s = Wh0; d = dh0; break;
        case 2:  s = W1;  d = d1;  break;
        default: s = Wh1; d = dh1; break;
    }
    float4 v = ((const float4*)s)[i];
    ((__half2*)d)[i * 2]     = __floats2half2_rn(v.x, v.y);
    ((__half2*)d)[i * 2 + 1] = __floats2half2_rn(v.z, v.w);
}

__global__ void cvtWd4_k(const float* __restrict__ src, __half* __restrict__ dst) {
    int i = blockIdx.x * blockDim.x + threadIdx.x;
    if (i >= NVP * KDIM / 4) return;
    int r = (i * 4) >> 10;
    float4 v = make_float4(0.f, 0.f, 0.f, 0.f);
    if (r < NV) v = ((const float4*)src)[i];
    ((__half2*)dst)[i * 2]     = __floats2half2_rn(v.x, v.y);
    ((__half2*)dst)[i * 2 + 1] = __floats2half2_rn(v.z, v.w);
}

__global__ void gatherX4_k(const float* __restrict__ emb, const int* __restrict__ inputs,
                           __half* __restrict__ dst) {
    int row = blockIdx.x;
    const float4* src = (const float4*)(emb + (size_t)inputs[row] * NE);
    __half2* d = (__half2*)(dst + (size_t)row * KDIM);
    int j = threadIdx.x;
    float4 v = src[j];
    d[j * 2]     = __floats2half2_rn(v.x, v.y);
    d[j * 2 + 1] = __floats2half2_rn(v.z, v.w);
}

__global__ void initH_k(const float* __restrict__ hidden) {
    int i = blockIdx.x * blockDim.x + threadIdx.x;
    if (i == 0) { g_bar0 = 0u; g_bar1 = 0u; g_tile = 0u; g_done = 0u; }
    if (i < NB * KDIM / 4) {
        float4 a = ((const float4*)hidden)[i];
        float4 b = ((const float4*)(hidden + NB * KDIM))[i];
        ((__half2*)g_h0i)[i * 2]     = __floats2half2_rn(a.x, a.y);
        ((__half2*)g_h0i)[i * 2 + 1] = __floats2half2_rn(a.z, a.w);
        ((__half2*)g_h1i)[i * 2]     = __floats2half2_rn(b.x, b.y);
        ((__half2*)g_h1i)[i * 2 + 1] = __floats2half2_rn(b.z, b.w);
    }
}

__global__ void write_hidden_k(float* __restrict__ out) {
    int i = blockIdx.x * blockDim.x + threadIdx.x;
    if (i < NB * KDIM) {
        out[i]             = __half2float(g_H0[(size_t)63 * NB * KDIM + i]);
        out[NB * KDIM + i] = __half2float(g_H1[(size_t)63 * NB * KDIM + i]);
    }
}

// ---------------------------------------------------------------------------
// GEMM tile body (R6-verified structure): C[bm..+128][bn..+128] for A@B^T+bias
// ---------------------------------------------------------------------------
#define SPITCH 40
#define STAGE_ELEMS (2 * 128 * SPITCH)
#define GEMM_SMEM (NSTAGE * STAGE_ELEMS * 2)

__device__ void gemm_tile(uint32_t sbase,
                          const __half* __restrict__ A, const __half* __restrict__ B,
                          const float* __restrict__ bias, float* __restrict__ C,
                          int Ntot, int bm, int bn, int tid, int lane, int wid)
{
    int wm = (wid & 3) * 32;
    int wn = (wid >> 2) * 64;

    float acc[2][8][4];
#pragma unroll
    for (int mt = 0; mt < 2; mt++)
#pragma unroll
        for (int nt = 0; nt < 8; nt++)
#pragma unroll
            for (int j = 0; j < 4; j++) acc[mt][nt][j] = 0.f;

    int lrow[2], lseg[2];
#pragma unroll
    for (int i = 0; i < 2; i++) {
        int u = tid + i * 256;
        lrow[i] = u >> 2;
        lseg[i] = u & 3;
    }

#pragma unroll
    for (int p = 0; p < NSTAGE - 1; p++) {
        uint32_t st = sbase + p * (STAGE_ELEMS * 2);
        int koff = p * 32;
#pragma unroll
        for (int i = 0; i < 2; i++) {
            uint32_t off = (uint32_t)(lrow[i] * SPITCH + lseg[i] * 8) * 2;
            cpasync16(st + off,                    A + (size_t)(bm + lrow[i]) * KDIM + koff + lseg[i] * 8);
            cpasync16(st + 128 * SPITCH * 2 + off, B + (size_t)(bn + lrow[i]) * KDIM + koff + lseg[i] * 8);
        }
        asm volatile("cp.async.commit_group;" ::: "memory");
    }

    for (int c = 0; c < NCH; c++) {
        asm volatile("cp.async.wait_group %0;" :: "n"(NSTAGE - 2) : "memory");
        __syncthreads();

        int cn = c + NSTAGE - 1;
        if (cn < NCH) {
            uint32_t st = sbase + (cn & (NSTAGE - 1)) * (STAGE_ELEMS * 2);
            int koff = cn * 32;
#pragma unroll
            for (int i = 0; i < 2; i++) {
                uint32_t off = (uint32_t)(lrow[i] * SPITCH + lseg[i] * 8) * 2;
                cpasync16(st + off,                    A + (size_t)(bm + lrow[i]) * KDIM + koff + lseg[i] * 8);
                cpasync16(st + 128 * SPITCH * 2 + off, B + (size_t)(bn + lrow[i]) * KDIM + koff + lseg[i] * 8);
            }
        }
        asm volatile("cp.async.commit_group;" ::: "memory");

        uint32_t sA = sbase + (c & (NSTAGE - 1)) * (STAGE_ELEMS * 2);
        uint32_t sB = sA + 128 * SPITCH * 2;
#pragma unroll
        for (int kk = 0; kk < 2; kk++) {
            uint32_t a[2][4], b[8][2];
#pragma unroll
            for (int mt = 0; mt < 2; mt++) {
                uint32_t addr = sA +
                    (uint32_t)((wm + mt * 16 + (lane & 15)) * SPITCH + kk * 16 + (lane >> 4) * 8) * 2;
                ldmat4(a[mt], addr);
            }
#pragma unroll
            for (int np = 0; np < 4; np++) {
                int brow = wn + np * 16 + (lane & 7) + ((lane & 16) ? 8 : 0);
                int bcol = kk * 16 + ((lane & 8) ? 8 : 0);
                uint32_t q[4];
                ldmat4(q, sB + (uint32_t)(brow * SPITCH + bcol) * 2);
                b[np * 2][0] = q[0]; b[np * 2][1] = q[1];
                b[np * 2 + 1][0] = q[2]; b[np * 2 + 1][1] = q[3];
            }
#pragma unroll
            for (int mt = 0; mt < 2; mt++)
#pragma unroll
                for (int nt = 0; nt < 8; nt++)
                    mma16816(acc[mt][nt], a[mt], b[nt]);
        }
    }

#pragma unroll
    for (int mt = 0; mt < 2; mt++) {
#pragma unroll
        for (int nt = 0; nt < 8; nt++) {
            int gcol = bn + wn + nt * 8 + (lane & 3) * 2;
            if (gcol >= Ntot) continue;
            float bx = bias[gcol], by = bias[gcol + 1];
            int r0 = bm + wm + mt * 16 + (lane >> 2);
            float2 v0 = make_float2(acc[mt][nt][0] + bx, acc[mt][nt][1] + by);
            float2 v1 = make_float2(acc[mt][nt][2] + bx, acc[mt][nt][3] + by);
            *(float2*)(C + (size_t)r0 * Ntot + gcol) = v0;
            *(float2*)(C + (size_t)(r0 + 8) * Ntot + gcol) = v1;
        }
    }
}

// standalone GEMM kernel (Xp projection)
__global__ void __launch_bounds__(256, 2) gemm_mma(
    const __half* __restrict__ A, const __half* __restrict__ B,
    const float* __restrict__ bias, float* __restrict__ C, int Ntot)
{
    extern __shared__ __half sm[];
    gemm_tile(smem_u32(sm), A, B, bias, C, Ntot,
              blockIdx.x * 128, blockIdx.y * 128,
              threadIdx.x, threadIdx.x & 31, threadIdx.x >> 5);
}

// ---------------------------------------------------------------------------
// Mega-kernel: fused dual chains + gated work-stealing logits GEMM.
// grid 148 x 256, 1 CTA/SM (co-resident). CTAs 0..63 h0-chain, 64..127
// h1-chain, 128..147 straight to GEMM. Logits tile (mt,nt) gated on
// bar1 >= (2*mt+2)*64. Counters reset by last CTA -> replay-idempotent.
// ---------------------------------------------------------------------------
#define CCOLS 16
#define HPITCH 1032
#define CHAIN_SMEM ((32 + NB) * HPITCH * 2)   // 198144 B (>= GEMM_SMEM)

__device__ __forceinline__ void chain_pass(uint32_t hsb, uint32_t wsb, int wrow0,
                                           int mw, int nw, int lane, float* acc) {
#pragma unroll 8
    for (int kk = 0; kk < 64; kk += 2) {
        uint32_t a0[4], b0[2], a1[4], b1[2];
        ldmat4(a0, hsb + (uint32_t)((mw * 16 + (lane & 15)) * HPITCH + kk * 16 + (lane >> 4) * 8) * 2);
        ldmat2(b0, wsb + (uint32_t)((wrow0 + nw * 8 + (lane & 7)) * HPITCH + kk * 16 + ((lane >> 3) & 1) * 8) * 2);
        ldmat4(a1, hsb + (uint32_t)((mw * 16 + (lane & 15)) * HPITCH + (kk + 1) * 16 + (lane >> 4) * 8) * 2);
        ldmat2(b1, wsb + (uint32_t)((wrow0 + nw * 8 + (lane & 7)) * HPITCH + (kk + 1) * 16 + ((lane >> 3) & 1) * 8) * 2);
        mma16816(acc, a0, b0);
        mma16816(acc + 4, a1, b1);
    }
}

__global__ void __launch_bounds__(256) mega_k(
    const float* __restrict__ Xp,
    const __half* __restrict__ h0i, const __half* __restrict__ h1i,
    const __half* __restrict__ Wh0, const __half* __restrict__ W1,
    const __half* __restrict__ Wh1, const float* __restrict__ b1,
    __half* __restrict__ H0, __half* __restrict__ H1,
    const __half* __restrict__ Wdh, const float* __restrict__ bd,
    float* __restrict__ out,
    unsigned int* __restrict__ bar0, unsigned int* __restrict__ bar1,
    unsigned int* __restrict__ tile, unsigned int* __restrict__ done)
{
    extern __shared__ __half smc[];
    __shared__ unsigned int s_tau;
    uint32_t wsb = smem_u32(smc);
    uint32_t hsb = wsb + 32 * HPITCH * 2;

    int tid  = threadIdx.x;
    int lane = tid & 31;
    int wid  = tid >> 5;
    int mw   = wid >> 1;
    int nw   = wid & 1;
    int bx   = blockIdx.x;

    if (bx < 128) {
        bool is1 = bx >= 64;
        int n0   = (bx & 63) * CCOLS;

        if (!is1) {
#pragma unroll
            for (int i = 0; i < 8; i++) {
                int u = tid + i * 256;
                int r = u >> 7, seg = u & 127;
                cpasync16(wsb + (uint32_t)(r * HPITCH + seg * 8) * 2,
                          Wh0 + (size_t)(n0 + r) * KDIM + seg * 8);
            }
        } else {
#pragma unroll
            for (int i = 0; i < 8; i++) {
                int u = tid + i * 256;
                int r = u >> 7, seg = u & 127;
                cpasync16(wsb + (uint32_t)(r * HPITCH + seg * 8) * 2,
                          Wh1 + (size_t)(n0 + r) * KDIM + seg * 8);
                cpasync16(wsb + (uint32_t)((16 + r) * HPITCH + seg * 8) * 2,
                          W1 + (size_t)(n0 + r) * KDIM + seg * 8);
            }
        }

        int r0 = mw * 16 + (lane >> 2);
        int c0 = n0 + nw * 8 + (lane & 3) * 2;
        float bb0 = 0.f, bb1 = 0.f;
        if (is1) { bb0 = b1[c0]; bb1 = b1[c0 + 1]; }

        if (!is1) {
            for (int t = 0; t < SQ; t++) {
                if (t > 0) {
                    if (tid == 0) spin_ge(bar0, (unsigned int)t * 64u);
                    __syncthreads();
                }
                const __half* hprev = (t == 0) ? h0i : H0 + (size_t)(t - 1) * NB * KDIM;
#pragma unroll
                for (int i = 0; i < 32; i++) {
                    int u = tid + i * 256;
                    int r = u >> 7, seg = u & 127;
                    cpasync16(hsb + (uint32_t)(r * HPITCH + seg * 8) * 2,
                              hprev + (size_t)r * KDIM + seg * 8);
                }
                asm volatile("cp.async.commit_group;" ::: "memory");
                asm volatile("cp.async.wait_group 0;" ::: "memory");
                __syncthreads();

                float acc[8] = {0.f,0.f,0.f,0.f,0.f,0.f,0.f,0.f};
                chain_pass(hsb, wsb, 0, mw, nw, lane, acc);

                const float* P_t = Xp + (size_t)t * NB * NH;
                __half* H_t = H0 + (size_t)t * NB * KDIM;
                float v0 = tanhf(P_t[r0 * NH + c0]           + acc[0] + acc[4]);
                float v1 = tanhf(P_t[r0 * NH + c0 + 1]       + acc[1] + acc[5]);
                float v2 = tanhf(P_t[(r0 + 8) * NH + c0]     + acc[2] + acc[6]);
                float v3 = tanhf(P_t[(r0 + 8) * NH + c0 + 1] + acc[3] + acc[7]);
                *(__half2*)(H_t + (size_t)r0 * KDIM + c0)       = __floats2half2_rn(v0, v1);
                *(__half2*)(H_t + (size_t)(r0 + 8) * KDIM + c0) = __floats2half2_rn(v2, v3);

                __syncthreads();
                if (tid == 0) red_release_add1(bar0);
            }
        } else {
            for (int t = 0; t < SQ; t++) {
                if (t > 0) {
                    if (tid == 0) spin_ge(bar1, (unsigned int)t * 64u);
                    __syncthreads();
                }
                const __half* hprev = (t == 0) ? h1i : H1 + (size_t)(t - 1) * NB * KDIM;
#pragma unroll
                for (int i = 0; i < 32; i++) {
                    int u = tid + i * 256;
                    int r = u >> 7, seg = u & 127;
                    cpasync16(hsb + (uint32_t)(r * HPITCH + seg * 8) * 2,
                              hprev + (size_t)r * KDIM + seg * 8);
                }
                asm volatile("cp.async.commit_group;" ::: "memory");
                asm volatile("cp.async.wait_group 0;" ::: "memory");
                __syncthreads();

                float acc[8] = {0.f,0.f,0.f,0.f,0.f,0.f,0.f,0.f};
                chain_pass(hsb, wsb, 0, mw, nw, lane, acc);
                __syncthreads();

                if (tid == 0) spin_ge(bar0, (unsigned int)(t + 1) * 64u);
                __syncthreads();
                const __half* h0t = H0 + (size_t)t * NB * KDIM;
#pragma unroll
                for (int i = 0; i < 32; i++) {
                    int u = tid + i * 256;
                    int r = u >> 7, seg = u & 127;
                    cpasync16(hsb + (uint32_t)(r * HPITCH + seg * 8) * 2,
                              h0t + (size_t)r * KDIM + seg * 8);
                }
                asm volatile("cp.async.commit_group;" ::: "memory");
                asm volatile("cp.async.wait_group 0;" ::: "memory");
                __syncthreads();

                chain_pass(hsb, wsb, 16, mw, nw, lane, acc);

                __half* H_t = H1 + (size_t)t * NB * KDIM;
                float v0 = tanhf(bb0 + acc[0] + acc[4]);
                float v1 = tanhf(bb1 + acc[1] + acc[5]);
                float v2 = tanhf(bb0 + acc[2] + acc[6]);
                float v3 = tanhf(bb1 + acc[3] + acc[7]);
                *(__half2*)(H_t + (size_t)r0 * KDIM + c0)       = __floats2half2_rn(v0, v1);
                *(__half2*)(H_t + (size_t)(r0 + 8) * KDIM + c0) = __floats2half2_rn(v2, v3);

                __syncthreads();
                if (tid == 0) red_release_add1(bar1);
            }
        }
    }
    __syncthreads();

    // ---- work-stealing logits GEMM, gated on h1 availability ----
    while (true) {
        if (tid == 0) s_tau = atomicAdd(tile, 1u);
        __syncthreads();
        unsigned int tau = s_tau;
        __syncthreads();
        if (tau >= (unsigned int)NTILES) break;
        int mt = (int)(tau / NT_N);
        int nt = (int)(tau % NT_N);
        if (tid == 0) spin_ge_sleep(bar1, (unsigned int)(2 * mt + 2) * 64u);
        __syncthreads();
        gemm_tile(wsb, H1, Wdh, bd, out, NV, mt * 128, nt * 128, tid, lane, wid);
        __syncthreads();
    }

    // completion + reset by last CTA -> replay-idempotent
    if (tid == 0) {
        unsigned int old = atomicAdd(done, 1u);
        if (old == 147u) {
            asm volatile("st.global.release.gpu.u32 [%0], %1;" :: "l"(bar0), "r"(0u) : "memory");
            asm volatile("st.global.release.gpu.u32 [%0], %1;" :: "l"(bar1), "r"(0u) : "memory");
            asm volatile("st.global.release.gpu.u32 [%0], %1;" :: "l"(tile), "r"(0u) : "memory");
            asm volatile("st.global.release.gpu.u32 [%0], %1;" :: "l"(done), "r"(0u) : "memory");
        }
    }
}

// ---------------------------------------------------------------------------
extern "C" void kernel_launch(void* const* d_in, const int* in_sizes, int n_in,
                              void* d_out, int out_size)
{
    const int*   inputs = (const int*)  d_in[0];
    const float* hidden = (const float*)d_in[1];
    const float* emb    = (const float*)d_in[2];
    const float* W0     = (const float*)d_in[3];
    const float* Wh0    = (const float*)d_in[4];
    const float* b0     = (const float*)d_in[5];
    const float* W1     = (const float*)d_in[6];
    const float* Wh1    = (const float*)d_in[7];
    const float* b1     = (const float*)d_in[8];
    const float* Wd     = (const float*)d_in[9];
    const float* bd     = (const float*)d_in[10];
    float* out = (float*)d_out;

    static bool inited = false;
    static float *pXp;
    static __half *pX, *pW0h, *pW1h, *pWh0h, *pWh1h, *pWdh, *pH0, *pH1, *ph0i, *ph1i;
    static unsigned int *pbar0, *pbar1, *ptile, *pdone;
    if (!inited) {
        cudaGetSymbolAddress((void**)&pXp,   g_Xp);
        cudaGetSymbolAddress((void**)&pX,    g_X);
        cudaGetSymbolAddress((void**)&pW0h,  g_W0h);
        cudaGetSymbolAddress((void**)&pW1h,  g_W1h);
        cudaGetSymbolAddress((void**)&pWh0h, g_Wh0h);
        cudaGetSymbolAddress((void**)&pWh1h, g_Wh1h);
        cudaGetSymbolAddress((void**)&pWdh,  g_Wdh);
        cudaGetSymbolAddress((void**)&pH0,   g_H0);
        cudaGetSymbolAddress((void**)&pH1,   g_H1);
        cudaGetSymbolAddress((void**)&ph0i,  g_h0i);
        cudaGetSymbolAddress((void**)&ph1i,  g_h1i);
        cudaGetSymbolAddress((void**)&pbar0, g_bar0);
        cudaGetSymbolAddress((void**)&pbar1, g_bar1);
        cudaGetSymbolAddress((void**)&ptile, g_tile);
        cudaGetSymbolAddress((void**)&pdone, g_done);
        cudaFuncSetAttribute(gemm_mma, cudaFuncAttributeMaxDynamicSharedMemorySize, GEMM_SMEM);
        cudaFuncSetAttribute(mega_k, cudaFuncAttributeMaxDynamicSharedMemorySize, CHAIN_SMEM);
        inited = true;
    }

    initH_k<<<(NB * KDIM / 4 + 255) / 256, 256>>>(hidden);

    { dim3 g(NH * KDIM / 4 / 256, 4);
      cvtW4_k<<<g, 256>>>(W0, Wh0, W1, Wh1, pW0h, pWh0h, pW1h, pWh1h); }
    cvtWd4_k<<<(NVP * KDIM / 4 + 255) / 256, 256>>>(Wd, pWdh);
    gatherX4_k<<<MROWS, 256>>>(emb, inputs, pX);

    // Xp = X @ W0^T + b0
    { dim3 g(MROWS / 128, NH / 128);
      gemm_mma<<<g, 256, GEMM_SMEM>>>(pX, pW0h, b0, pXp, NH); }

    // fused chains + gated logits GEMM (one persistent launch)
    mega_k<<<148, 256, CHAIN_SMEM>>>(pXp, ph0i, ph1i, pWh0h, pW1h, pWh1h, b1,
                                     pH0, pH1, pWdh, bd, out,
                                     pbar0, pbar1, ptile, pdone);

    if ((long long)out_size >= (long long)SQ * NB * NV + 2LL * NB * KDIM)
        write_hidden_k<<<(NB * KDIM + 255) / 256, 256>>>(out + (size_t)SQ * NB * NV);
}

// round 17
// speedup vs baseline: 1.2592x; 1.2592x over previous
#include <cuda_runtime.h>
#include <cuda_fp16.h>
#include <math.h>
#include <stdint.h>

#define SQ 64
#define NB 64
#define NV 10000
#define NVP 10112            // padded to 79*128
#define NE 1024
#define NH 1024
#define MROWS (SQ*NB)        // 4096
#define KDIM 1024
#define NCH 32               // 1024/32 k-chunks
#define NSTAGE 4

// ---------------------------------------------------------------------------
// Device scratch
// ---------------------------------------------------------------------------
__device__ float  g_Xp[MROWS * NH];          // x@W0^T + b0
__device__ __half g_X[MROWS * KDIM];         // gathered emb
__device__ __half g_W0h[NH * KDIM];
__device__ __half g_W1h[NH * KDIM];
__device__ __half g_Wh0h[NH * KDIM];
__device__ __half g_Wh1h[NH * KDIM];
__device__ __half g_Wdh[NVP * KDIM];
__device__ __half g_H0[MROWS * KDIM];        // h0 history
__device__ __half g_H1[MROWS * KDIM];        // h1 history
__device__ __half g_h0i[NB * KDIM];
__device__ __half g_h1i[NB * KDIM];
__device__ unsigned int g_bar0 = 0;
__device__ unsigned int g_bar1 = 0;
__device__ unsigned int g_bar2 = 0;

// ---------------------------------------------------------------------------
// helpers
// ---------------------------------------------------------------------------
__device__ __forceinline__ uint32_t smem_u32(const void* p) {
    uint32_t a;
    asm("{ .reg .u64 t; cvta.to.shared.u64 t, %1; cvt.u32.u64 %0, t; }" : "=r"(a) : "l"(p));
    return a;
}
__device__ __forceinline__ void cpasync16(uint32_t dst, const void* src) {
    asm volatile("cp.async.cg.shared.global [%0], [%1], 16;" :: "r"(dst), "l"(src) : "memory");
}
__device__ __forceinline__ void ldmat4(uint32_t* r, uint32_t addr) {
    asm volatile("ldmatrix.sync.aligned.m8n8.x4.shared.b16 {%0,%1,%2,%3}, [%4];"
                 : "=r"(r[0]), "=r"(r[1]), "=r"(r[2]), "=r"(r[3]) : "r"(addr));
}
__device__ __forceinline__ void ldmat2(uint32_t* r, uint32_t addr) {
    asm volatile("ldmatrix.sync.aligned.m8n8.x2.shared.b16 {%0,%1}, [%2];"
                 : "=r"(r[0]), "=r"(r[1]) : "r"(addr));
}
__device__ __forceinline__ void mma16816(float* c, const uint32_t* a, const uint32_t* b) {
    asm volatile("mma.sync.aligned.m16n8k16.row.col.f32.f16.f16.f32 "
                 "{%0,%1,%2,%3}, {%4,%5,%6,%7}, {%8,%9}, {%0,%1,%2,%3};"
                 : "+f"(c[0]), "+f"(c[1]), "+f"(c[2]), "+f"(c[3])
                 : "r"(a[0]), "r"(a[1]), "r"(a[2]), "r"(a[3]), "r"(b[0]), "r"(b[1]));
}
// tight spin on the chain critical path (one polling thread per CTA)
__device__ __forceinline__ void spin_ge(const unsigned int* bar, unsigned int target) {
    unsigned int v;
    do {
        asm volatile("ld.global.acquire.gpu.u32 %0, [%1];" : "=r"(v) : "l"(bar) : "memory");
    } while (v < target);
}
// release-reduction publish (replaces __threadfence + atomicAdd)
__device__ __forceinline__ void red_release_add1(unsigned int* bar) {
    asm volatile("red.release.gpu.global.add.u32 [%0], %1;" :: "l"(bar), "r"(1u) : "memory");
}

// ---------------------------------------------------------------------------
// conversion / init kernels (vectorized)
// ---------------------------------------------------------------------------
__global__ void cvtW4_k(const float* __restrict__ W0, const float* __restrict__ Wh0,
                        const float* __restrict__ W1, const float* __restrict__ Wh1,
                        __half* __restrict__ d0, __half* __restrict__ dh0,
                        __half* __restrict__ d1, __half* __restrict__ dh1) {
    int i = blockIdx.x * blockDim.x + threadIdx.x;    // 0 .. NH*KDIM/4-1
    const float* s; __half* d;
    switch (blockIdx.y) {
        case 0:  s = W0;  d = d0;  break;
        case 1:  s = Wh0; d = dh0; break;
        case 2:  s = W1;  d = d1;  break;
        default: s = Wh1; d = dh1; break;
    }
    float4 v = ((const float4*)s)[i];
    ((__half2*)d)[i * 2]     = __floats2half2_rn(v.x, v.y);
    ((__half2*)d)[i * 2 + 1] = __floats2half2_rn(v.z, v.w);
}

__global__ void cvtWd4_k(const float* __restrict__ src, __half* __restrict__ dst) {
    int i = blockIdx.x * blockDim.x + threadIdx.x;    // 0 .. NVP*KDIM/4-1
    if (i >= NVP * KDIM / 4) return;
    int r = (i * 4) >> 10;
    float4 v = make_float4(0.f, 0.f, 0.f, 0.f);
    if (r < NV) v = ((const float4*)src)[i];
    ((__half2*)dst)[i * 2]     = __floats2half2_rn(v.x, v.y);
    ((__half2*)dst)[i * 2 + 1] = __floats2half2_rn(v.z, v.w);
}

__global__ void gatherX4_k(const float* __restrict__ emb, const int* __restrict__ inputs,
                           __half* __restrict__ dst) {
    int row = blockIdx.x;
    const float4* src = (const float4*)(emb + (size_t)inputs[row] * NE);
    __half2* d = (__half2*)(dst + (size_t)row * KDIM);
    int j = threadIdx.x;                               // 0..255, NE/4=256
    float4 v = src[j];
    d[j * 2]     = __floats2half2_rn(v.x, v.y);
    d[j * 2 + 1] = __floats2half2_rn(v.z, v.w);
}

__global__ void initH_k(const float* __restrict__ hidden) {
    int i = blockIdx.x * blockDim.x + threadIdx.x;    // NB*KDIM/4 threads
    if (i == 0) { g_bar0 = 0u; g_bar1 = 0u; g_bar2 = 0u; }
    if (i < NB * KDIM / 4) {
        float4 a = ((const float4*)hidden)[i];
        float4 b = ((const float4*)(hidden + NB * KDIM))[i];
        ((__half2*)g_h0i)[i * 2]     = __floats2half2_rn(a.x, a.y);
        ((__half2*)g_h0i)[i * 2 + 1] = __floats2half2_rn(a.z, a.w);
        ((__half2*)g_h1i)[i * 2]     = __floats2half2_rn(b.x, b.y);
        ((__half2*)g_h1i)[i * 2 + 1] = __floats2half2_rn(b.z, b.w);
    }
}

__global__ void write_hidden_k(float* __restrict__ out) {
    int i = blockIdx.x * blockDim.x + threadIdx.x;
    if (i < NB * KDIM) {
        out[i]             = __half2float(g_H0[(size_t)63 * NB * KDIM + i]);
        out[NB * KDIM + i] = __half2float(g_H1[(size_t)63 * NB * KDIM + i]);
    }
}

// ---------------------------------------------------------------------------
// fp16 mma.sync GEMM, 4-stage cp.async pipeline (R6-verified config).
// CTA 128x128, 8 warps (32x64), K-chunk 32. grid=(M/128, rowsPad/128), 256 thr.
// ---------------------------------------------------------------------------
#define SPITCH 40
#define STAGE_ELEMS (2 * 128 * SPITCH)
#define GEMM_SMEM (NSTAGE * STAGE_ELEMS * 2)

__global__ void __launch_bounds__(256, 2) gemm_mma(
    const __half* __restrict__ A, const __half* __restrict__ B,
    const float* __restrict__ bias, float* __restrict__ C, int Ntot)
{
    extern __shared__ __half sm[];
    uint32_t sbase = smem_u32(sm);

    int tid  = threadIdx.x;
    int lane = tid & 31;
    int wid  = tid >> 5;
    int wm   = (wid & 3) * 32;
    int wn   = (wid >> 2) * 64;
    int bm   = blockIdx.x * 128;
    int bn   = blockIdx.y * 128;

    float acc[2][8][4];
#pragma unroll
    for (int mt = 0; mt < 2; mt++)
#pragma unroll
        for (int nt = 0; nt < 8; nt++)
#pragma unroll
            for (int j = 0; j < 4; j++) acc[mt][nt][j] = 0.f;

    int lrow[2], lseg[2];
#pragma unroll
    for (int i = 0; i < 2; i++) {
        int u = tid + i * 256;
        lrow[i] = u >> 2;
        lseg[i] = u & 3;
    }

#pragma unroll
    for (int p = 0; p < NSTAGE - 1; p++) {
        uint32_t st = sbase + p * (STAGE_ELEMS * 2);
        int koff = p * 32;
#pragma unroll
        for (int i = 0; i < 2; i++) {
            uint32_t off = (uint32_t)(lrow[i] * SPITCH + lseg[i] * 8) * 2;
            cpasync16(st + off,                    A + (size_t)(bm + lrow[i]) * KDIM + koff + lseg[i] * 8);
            cpasync16(st + 128 * SPITCH * 2 + off, B + (size_t)(bn + lrow[i]) * KDIM + koff + lseg[i] * 8);
        }
        asm volatile("cp.async.commit_group;" ::: "memory");
    }

    for (int c = 0; c < NCH; c++) {
        asm volatile("cp.async.wait_group %0;" :: "n"(NSTAGE - 2) : "memory");
        __syncthreads();

        int cn = c + NSTAGE - 1;
        if (cn < NCH) {
            uint32_t st = sbase + (cn & (NSTAGE - 1)) * (STAGE_ELEMS * 2);
            int koff = cn * 32;
#pragma unroll
            for (int i = 0; i < 2; i++) {
                uint32_t off = (uint32_t)(lrow[i] * SPITCH + lseg[i] * 8) * 2;
                cpasync16(st + off,                    A + (size_t)(bm + lrow[i]) * KDIM + koff + lseg[i] * 8);
                cpasync16(st + 128 * SPITCH * 2 + off, B + (size_t)(bn + lrow[i]) * KDIM + koff + lseg[i] * 8);
            }
        }
        asm volatile("cp.async.commit_group;" ::: "memory");

        uint32_t sA = sbase + (c & (NSTAGE - 1)) * (STAGE_ELEMS * 2);
        uint32_t sB = sA + 128 * SPITCH * 2;
#pragma unroll
        for (int kk = 0; kk < 2; kk++) {
            uint32_t a[2][4], b[8][2];
#pragma unroll
            for (int mt = 0; mt < 2; mt++) {
                uint32_t addr = sA +
                    (uint32_t)((wm + mt * 16 + (lane & 15)) * SPITCH + kk * 16 + (lane >> 4) * 8) * 2;
                ldmat4(a[mt], addr);
            }
#pragma unroll
            for (int np = 0; np < 4; np++) {
                int brow = wn + np * 16 + (lane & 7) + ((lane & 16) ? 8 : 0);
                int bcol = kk * 16 + ((lane & 8) ? 8 : 0);
                uint32_t q[4];
                ldmat4(q, sB + (uint32_t)(brow * SPITCH + bcol) * 2);
                b[np * 2][0] = q[0]; b[np * 2][1] = q[1];
                b[np * 2 + 1][0] = q[2]; b[np * 2 + 1][1] = q[3];
            }
#pragma unroll
            for (int mt = 0; mt < 2; mt++)
#pragma unroll
                for (int nt = 0; nt < 8; nt++)
                    mma16816(acc[mt][nt], a[mt], b[nt]);
        }
    }

#pragma unroll
    for (int mt = 0; mt < 2; mt++) {
#pragma unroll
        for (int nt = 0; nt < 8; nt++) {
            int gcol = bn + wn + nt * 8 + (lane & 3) * 2;
            if (gcol >= Ntot) continue;
            float bx = bias[gcol], by = bias[gcol + 1];
            int r0 = bm + wm + mt * 16 + (lane >> 2);
            float2 v0 = make_float2(acc[mt][nt][0] + bx, acc[mt][nt][1] + by);
            float2 v1 = make_float2(acc[mt][nt][2] + bx, acc[mt][nt][3] + by);
            *(float2*)(C + (size_t)r0 * Ntot + gcol) = v0;
            *(float2*)(C + (size_t)(r0 + 8) * Ntot + gcol) = v1;
        }
    }
}

// ---------------------------------------------------------------------------
// Fused dual-chain persistent kernel (R11 structure). 128 CTAs x 256 threads.
//   CTAs 0..63   : h0 chain (16 cols each), Wh0 slice resident.
//   CTAs 64..127 : h1 chain, one step behind, Wh1 + W1 slices resident.
// Publish via red.release; tight acquire spins. Reset via bar2 -> idempotent.
// ---------------------------------------------------------------------------
#define CCOLS 16
#define HPITCH 1032          // halves; 2064B pitch -> conflict-free ldmatrix
#define CHAIN_SMEM ((32 + NB) * HPITCH * 2)   // 198144 B

__device__ __forceinline__ void chain_pass(uint32_t hsb, uint32_t wsb, int wrow0,
                                           int mw, int nw, int lane, float* acc) {
#pragma unroll 8
    for (int kk = 0; kk < 64; kk += 2) {
        uint32_t a0[4], b0[2], a1[4], b1[2];
        ldmat4(a0, hsb + (uint32_t)((mw * 16 + (lane & 15)) * HPITCH + kk * 16 + (lane >> 4) * 8) * 2);
        ldmat2(b0, wsb + (uint32_t)((wrow0 + nw * 8 + (lane & 7)) * HPITCH + kk * 16 + ((lane >> 3) & 1) * 8) * 2);
        ldmat4(a1, hsb + (uint32_t)((mw * 16 + (lane & 15)) * HPITCH + (kk + 1) * 16 + (lane >> 4) * 8) * 2);
        ldmat2(b1, wsb + (uint32_t)((wrow0 + nw * 8 + (lane & 7)) * HPITCH + (kk + 1) * 16 + ((lane >> 3) & 1) * 8) * 2);
        mma16816(acc, a0, b0);
        mma16816(acc + 4, a1, b1);
    }
}

__global__ void __launch_bounds__(256) chain_fused_k(
    const float* __restrict__ Xp,
    const __half* __restrict__ h0i, const __half* __restrict__ h1i,
    const __half* __restrict__ Wh0, const __half* __restrict__ W1,
    const __half* __restrict__ Wh1, const float* __restrict__ b1,
    __half* __restrict__ H0, __half* __restrict__ H1,
    unsigned int* __restrict__ bar0, unsigned int* __restrict__ bar1,
    unsigned int* __restrict__ bar2)
{
    extern __shared__ __half smc[];
    uint32_t wsb = smem_u32(smc);                    // 32 rows of W
    uint32_t hsb = wsb + 32 * HPITCH * 2;            // 64 rows of h

    int tid  = threadIdx.x;
    int lane = tid & 31;
    int wid  = tid >> 5;
    int mw   = wid >> 1;
    int nw   = wid & 1;
    bool is1 = blockIdx.x >= 64;
    int n0   = (blockIdx.x & 63) * CCOLS;

    if (!is1) {
#pragma unroll
        for (int i = 0; i < 8; i++) {
            int u = tid + i * 256;
            int r = u >> 7, seg = u & 127;
            cpasync16(wsb + (uint32_t)(r * HPITCH + seg * 8) * 2,
                      Wh0 + (size_t)(n0 + r) * KDIM + seg * 8);
        }
    } else {
#pragma unroll
        for (int i = 0; i < 8; i++) {
            int u = tid + i * 256;
            int r = u >> 7, seg = u & 127;
            cpasync16(wsb + (uint32_t)(r * HPITCH + seg * 8) * 2,
                      Wh1 + (size_t)(n0 + r) * KDIM + seg * 8);
            cpasync16(wsb + (uint32_t)((16 + r) * HPITCH + seg * 8) * 2,
                      W1 + (size_t)(n0 + r) * KDIM + seg * 8);
        }
    }

    int r0 = mw * 16 + (lane >> 2);
    int c0 = n0 + nw * 8 + (lane & 3) * 2;
    float bb0 = 0.f, bb1 = 0.f;
    if (is1) { bb0 = b1[c0]; bb1 = b1[c0 + 1]; }

    if (!is1) {
        // ---------------- h0 chain ----------------
        for (int t = 0; t < SQ; t++) {
            if (t > 0) {
                if (tid == 0) spin_ge(bar0, (unsigned int)t * 64u);
                __syncthreads();
            }
            const __half* hprev = (t == 0) ? h0i : H0 + (size_t)(t - 1) * NB * KDIM;
#pragma unroll
            for (int i = 0; i < 32; i++) {
                int u = tid + i * 256;
                int r = u >> 7, seg = u & 127;
                cpasync16(hsb + (uint32_t)(r * HPITCH + seg * 8) * 2,
                          hprev + (size_t)r * KDIM + seg * 8);
            }
            asm volatile("cp.async.commit_group;" ::: "memory");
            asm volatile("cp.async.wait_group 0;" ::: "memory");
            __syncthreads();

            float acc[8] = {0.f,0.f,0.f,0.f,0.f,0.f,0.f,0.f};
            chain_pass(hsb, wsb, 0, mw, nw, lane, acc);

            const float* P_t = Xp + (size_t)t * NB * NH;
            __half* H_t = H0 + (size_t)t * NB * KDIM;
            float v0 = tanhf(P_t[r0 * NH + c0]           + acc[0] + acc[4]);
            float v1 = tanhf(P_t[r0 * NH + c0 + 1]       + acc[1] + acc[5]);
            float v2 = tanhf(P_t[(r0 + 8) * NH + c0]     + acc[2] + acc[6]);
            float v3 = tanhf(P_t[(r0 + 8) * NH + c0 + 1] + acc[3] + acc[7]);
            *(__half2*)(H_t + (size_t)r0 * KDIM + c0)       = __floats2half2_rn(v0, v1);
            *(__half2*)(H_t + (size_t)(r0 + 8) * KDIM + c0) = __floats2half2_rn(v2, v3);

            __syncthreads();                 // all stores done + hsm reuse guard
            if (tid == 0) red_release_add1(bar0);
        }
    } else {
        // ---------------- h1 chain (one step behind) ----------------
        for (int t = 0; t < SQ; t++) {
            if (t > 0) {
                if (tid == 0) spin_ge(bar1, (unsigned int)t * 64u);
                __syncthreads();
            }
            const __half* hprev = (t == 0) ? h1i : H1 + (size_t)(t - 1) * NB * KDIM;
#pragma unroll
            for (int i = 0; i < 32; i++) {
                int u = tid + i * 256;
                int r = u >> 7, seg = u & 127;
                cpasync16(hsb + (uint32_t)(r * HPITCH + seg * 8) * 2,
                          hprev + (size_t)r * KDIM + seg * 8);
            }
            asm volatile("cp.async.commit_group;" ::: "memory");
            asm volatile("cp.async.wait_group 0;" ::: "memory");
            __syncthreads();

            float acc[8] = {0.f,0.f,0.f,0.f,0.f,0.f,0.f,0.f};
            chain_pass(hsb, wsb, 0, mw, nw, lane, acc);
            __syncthreads();                        // done reading hsm

            if (tid == 0) spin_ge(bar0, (unsigned int)(t + 1) * 64u);
            __syncthreads();
            const __half* h0t = H0 + (size_t)t * NB * KDIM;
#pragma unroll
            for (int i = 0; i < 32; i++) {
                int u = tid + i * 256;
                int r = u >> 7, seg = u & 127;
                cpasync16(hsb + (uint32_t)(r * HPITCH + seg * 8) * 2,
                          h0t + (size_t)r * KDIM + seg * 8);
            }
            asm volatile("cp.async.commit_group;" ::: "memory");
            asm volatile("cp.async.wait_group 0;" ::: "memory");
            __syncthreads();

            chain_pass(hsb, wsb, 16, mw, nw, lane, acc);

            __half* H_t = H1 + (size_t)t * NB * KDIM;
            float v0 = tanhf(bb0 + acc[0] + acc[4]);
            float v1 = tanhf(bb1 + acc[1] + acc[5]);
            float v2 = tanhf(bb0 + acc[2] + acc[6]);
            float v3 = tanhf(bb1 + acc[3] + acc[7]);
            *(__half2*)(H_t + (size_t)r0 * KDIM + c0)       = __floats2half2_rn(v0, v1);
            *(__half2*)(H_t + (size_t)(r0 + 8) * KDIM + c0) = __floats2half2_rn(v2, v3);

            __syncthreads();
            if (tid == 0) red_release_add1(bar1);
        }
    }

    // completion + single reset -> replay-idempotent
    if (tid == 0) {
        atomicAdd(bar2, 1u);
        if (blockIdx.x == 0) {
            spin_ge(bar2, 128u);
            asm volatile("st.global.release.gpu.u32 [%0], %1;" :: "l"(bar0), "r"(0u) : "memory");
            asm volatile("st.global.release.gpu.u32 [%0], %1;" :: "l"(bar1), "r"(0u) : "memory");
            asm volatile("st.global.release.gpu.u32 [%0], %1;" :: "l"(bar2), "r"(0u) : "memory");
        }
    }
}

// ---------------------------------------------------------------------------
extern "C" void kernel_launch(void* const* d_in, const int* in_sizes, int n_in,
                              void* d_out, int out_size)
{
    const int*   inputs = (const int*)  d_in[0];
    const float* hidden = (const float*)d_in[1];
    const float* emb    = (const float*)d_in[2];
    const float* W0     = (const float*)d_in[3];
    const float* Wh0    = (const float*)d_in[4];
    const float* b0     = (const float*)d_in[5];
    const float* W1     = (const float*)d_in[6];
    const float* Wh1    = (const float*)d_in[7];
    const float* b1     = (const float*)d_in[8];
    const float* Wd     = (const float*)d_in[9];
    const float* bd     = (const float*)d_in[10];
    float* out = (float*)d_out;

    static bool inited = false;
    static float *pXp;
    static __half *pX, *pW0h, *pW1h, *pWh0h, *pWh1h, *pWdh, *pH0, *pH1, *ph0i, *ph1i;
    static unsigned int *pbar0, *pbar1, *pbar2;
    if (!inited) {
        cudaGetSymbolAddress((void**)&pXp,   g_Xp);
        cudaGetSymbolAddress((void**)&pX,    g_X);
        cudaGetSymbolAddress((void**)&pW0h,  g_W0h);
        cudaGetSymbolAddress((void**)&pW1h,  g_W1h);
        cudaGetSymbolAddress((void**)&pWh0h, g_Wh0h);
        cudaGetSymbolAddress((void**)&pWh1h, g_Wh1h);
        cudaGetSymbolAddress((void**)&pWdh,  g_Wdh);
        cudaGetSymbolAddress((void**)&pH0,   g_H0);
        cudaGetSymbolAddress((void**)&pH1,   g_H1);
        cudaGetSymbolAddress((void**)&ph0i,  g_h0i);
        cudaGetSymbolAddress((void**)&ph1i,  g_h1i);
        cudaGetSymbolAddress((void**)&pbar0, g_bar0);
        cudaGetSymbolAddress((void**)&pbar1, g_bar1);
        cudaGetSymbolAddress((void**)&pbar2, g_bar2);
        cudaFuncSetAttribute(gemm_mma, cudaFuncAttributeMaxDynamicSharedMemorySize, GEMM_SMEM);
        cudaFuncSetAttribute(chain_fused_k, cudaFuncAttributeMaxDynamicSharedMemorySize, CHAIN_SMEM);
        inited = true;
    }

    initH_k<<<(NB * KDIM / 4 + 255) / 256, 256>>>(hidden);

    { dim3 g(NH * KDIM / 4 / 256, 4);
      cvtW4_k<<<g, 256>>>(W0, Wh0, W1, Wh1, pW0h, pWh0h, pW1h, pWh1h); }
    cvtWd4_k<<<(NVP * KDIM / 4 + 255) / 256, 256>>>(Wd, pWdh);
    gatherX4_k<<<MROWS, 256>>>(emb, inputs, pX);

    // Xp = X @ W0^T + b0
    { dim3 g(MROWS / 128, NH / 128);
      gemm_mma<<<g, 256, GEMM_SMEM>>>(pX, pW0h, b0, pXp, NH); }

    // fused h0 + h1 chains (one persistent launch)
    chain_fused_k<<<128, 256, CHAIN_SMEM>>>(pXp, ph0i, ph1i, pWh0h, pW1h, pWh1h,
                                            b1, pH0, pH1, pbar0, pbar1, pbar2);

    // logits = H1 @ Wd^T + bd (standalone, 2 CTA/SM)
    { dim3 g(MROWS / 128, NVP / 128);
      gemm_mma<<<g, 256, GEMM_SMEM>>>(pH1, pWdh, bd, out, NV); }

    if ((long long)out_size >= (long long)SQ * NB * NV + 2LL * NB * KDIM)
        write_hidden_k<<<(NB * KDIM + 255) / 256, 256>>>(out + (size_t)SQ * NB * NV);
}